// round 15
// baseline (speedup 1.0000x reference)
#include <cuda_runtime.h>
#include <cuda_fp16.h>
#include <cstdint>

#define DH 64
#define BM 128
#define BN 64
#define SKB 144          // smem row stride bytes (72 fp16) -> ldmatrix conflict-free

#define SM_QH  0
#define SM_KH  (BM*SKB)               // 18432
#define SM_VH  (SM_KH + BN*SKB)       // 27648
#define SM_TOTAL (SM_VH + BN*SKB)     // 36864 B -> 2 CTAs/SM

#define MAXROWS 16384
#define NCH_MAX 4

__device__ float g_Opart[(size_t)NCH_MAX * MAXROWS * DH];
__device__ float g_lpart[(size_t)NCH_MAX * MAXROWS];
__device__ uint4 g_Kh[(size_t)MAXROWS * DH / 8];
__device__ uint4 g_Vh[(size_t)MAXROWS * DH / 8];

static __device__ __forceinline__ uint32_t smem_u32(const void* p){
    uint32_t a;
    asm("{ .reg .u64 t; cvta.to.shared.u64 t, %1; cvt.u32.u64 %0, t; }" : "=r"(a) : "l"(p));
    return a;
}
static __device__ __forceinline__ uint32_t cvt2h(float a, float b){
    __half2 h = __floats2half2_rn(a, b);
    return *reinterpret_cast<uint32_t*>(&h);
}
static __device__ __forceinline__ uint32_t ex2h2(uint32_t x){
    uint32_t r;
    asm("ex2.approx.f16x2 %0, %1;" : "=r"(r) : "r"(x));
    return r;
}
static __device__ __forceinline__ void cvtH8(const float* f, uint4& out){
    out = make_uint4(cvt2h(f[0], f[1]), cvt2h(f[2], f[3]),
                     cvt2h(f[4], f[5]), cvt2h(f[6], f[7]));
}
static __device__ __forceinline__ void ldsm4(uint32_t* r, uint32_t a){
    asm volatile("ldmatrix.sync.aligned.m8n8.x4.shared.b16 {%0,%1,%2,%3}, [%4];"
                 : "=r"(r[0]), "=r"(r[1]), "=r"(r[2]), "=r"(r[3]) : "r"(a));
}
static __device__ __forceinline__ void ldsm4t(uint32_t* r, uint32_t a){
    asm volatile("ldmatrix.sync.aligned.m8n8.x4.trans.shared.b16 {%0,%1,%2,%3}, [%4];"
                 : "=r"(r[0]), "=r"(r[1]), "=r"(r[2]), "=r"(r[3]) : "r"(a));
}
static __device__ __forceinline__ void mma16816(float* d, const uint32_t* a, uint32_t b0, uint32_t b1){
    asm volatile("mma.sync.aligned.m16n8k16.row.col.f32.f16.f16.f32 "
                 "{%0,%1,%2,%3}, {%4,%5,%6,%7}, {%8,%9}, {%0,%1,%2,%3};"
                 : "+f"(d[0]), "+f"(d[1]), "+f"(d[2]), "+f"(d[3])
                 : "r"(a[0]), "r"(a[1]), "r"(a[2]), "r"(a[3]), "r"(b0), "r"(b1));
}

// ---------------- Phase 0: convert K,V fp32 -> fp16 (only rows part will read) ----------------
// Thread i handles uint4 index i of K AND of V: 4 LDG.128 in flight, 2 STG.128.
__global__ __launch_bounds__(256, 8)
void fa_cvt_kernel(const float* __restrict__ K, const float* __restrict__ V,
                   const int* __restrict__ vlen, int Lk, int n8)
{
    const int j = blockIdx.x * blockDim.x + threadIdx.x;
    if (j >= n8) return;
    const int row  = j >> 3;            // DH/8 = 8 uint4 per row
    const int b    = row / Lk;
    const int rloc = row - b * Lk;
    int vl = vlen[b];
    if (vl < 1) vl = 1;
    if (vl > Lk) vl = Lk;
    const int thr = ((vl + BN - 1) / BN) * BN;   // tile-rounded: rows part may touch
    if (rloc >= thr) return;

    const float4* K4 = (const float4*)K;
    const float4* V4 = (const float4*)V;
    float4 a0 = K4[(size_t)j*2], a1 = K4[(size_t)j*2+1];
    float4 b0 = V4[(size_t)j*2], b1 = V4[(size_t)j*2+1];
    float f[8]; uint4 u;
    *(float4*)(f) = a0; *(float4*)(f+4) = a1; cvtH8(f, u); g_Kh[j] = u;
    *(float4*)(f) = b0; *(float4*)(f+4) = b1; cvtH8(f, u); g_Vh[j] = u;
}

// ---------------- Phase 1: partial attention over one key chunk ----------------
__global__ __launch_bounds__(256, 2)
void fa_part_kernel(const float* __restrict__ Q, const int* __restrict__ vlen,
                    float* __restrict__ O, int Lq, int Lk, int ck)
{
    extern __shared__ char smem[];
    const uint32_t sb = smem_u32(smem);
    const int t  = threadIdx.x;
    const int w  = t >> 5;
    const int ln = t & 31;
    const int g  = ln >> 2;
    const int tg = ln & 3;
    const int b  = blockIdx.y;
    const int q0 = blockIdx.x * BM;
    const int c  = blockIdx.z;

    int vl = vlen[b];
    if (vl < 1) vl = 1;
    if (vl > Lk) vl = Lk;
    const int nact = (vl + ck - 1) / ck;

    const int cstart = c * ck;
    if (cstart >= vl) return;
    const int kend   = (cstart + ck < vl) ? cstart + ck : vl;
    const int ntiles = (kend - cstart + BN - 1) / BN;

    const int B_ = gridDim.y;
    const int R  = B_ * Lq;

    const float* Qb = Q + ((size_t)b * Lq + q0) * DH;
    const uint4* Kb = g_Kh + ((size_t)b * Lk + cstart) * (DH / 8);
    const uint4* Vb = g_Vh + ((size_t)b * Lk + cstart) * (DH / 8);

    // ---- Q -> smem, pre-scaled by log2e/sqrt(d), single fp16 ----
    {
        int r = t >> 1, h = t & 1;
        const float* qp = Qb + (size_t)r * DH + h * 32;
        float f[32];
        #pragma unroll
        for (int i = 0; i < 8; i++) *(float4*)(f + 4*i) = *(const float4*)(qp + 4*i);
        #pragma unroll
        for (int i = 0; i < 32; i++) f[i] *= 0.18033688f;   // 1.4426950f / 8
        #pragma unroll
        for (int cc = 0; cc < 4; cc++){
            uint4 u; cvtH8(f + 8*cc, u);
            *(uint4*)(smem + SM_QH + r * SKB + (h*4 + cc) * 16) = u;
        }
    }
    __syncthreads();

    // ---- Q A-fragments ----
    uint32_t qh[4][4];
    {
        uint32_t rowoff = (uint32_t)(16*w + (ln & 15)) * SKB + (uint32_t)(ln >> 4) * 16;
        #pragma unroll
        for (int ks = 0; ks < 4; ks++)
            ldsm4(qh[ks], sb + SM_QH + rowoff + ks * 32);
    }

    float oc[8][4];
    #pragma unroll
    for (int nt = 0; nt < 8; nt++)
        #pragma unroll
        for (int j = 0; j < 4; j++) oc[nt][j] = 0.f;
    float lc[4] = {0.f, 0.f, 0.f, 0.f};
    const uint32_t HONES = 0x3C003C00u;   // half2(1,1)

    // ---- prefetch tile 0 ----
    const int r4 = t >> 2, qq = t & 3;
    uint4 ku[2], vu[2];
    {
        const uint4* kp = Kb + (size_t)r4 * (DH / 8) + qq * 2;
        const uint4* vp = Vb + (size_t)r4 * (DH / 8) + qq * 2;
        ku[0] = kp[0]; ku[1] = kp[1];
        vu[0] = vp[0]; vu[1] = vp[1];
    }

    for (int kt = 0; kt < ntiles; kt++){
        const int n0g = cstart + kt * BN;

        __syncthreads();
        {
            int off = r4 * SKB + qq * 32;
            *(uint4*)(smem + SM_KH + off)      = ku[0];
            *(uint4*)(smem + SM_KH + off + 16) = ku[1];
            *(uint4*)(smem + SM_VH + off)      = vu[0];
            *(uint4*)(smem + SM_VH + off + 16) = vu[1];
        }
        __syncthreads();

        if (kt + 1 < ntiles){
            const uint4* kp = Kb + (size_t)((kt+1)*BN + r4) * (DH / 8) + qq * 2;
            const uint4* vp = Vb + (size_t)((kt+1)*BN + r4) * (DH / 8) + qq * 2;
            ku[0] = kp[0]; ku[1] = kp[1];
            vu[0] = vp[0]; vu[1] = vp[1];
        }

        // ---- fused S-MMA + fp16 exp epilogue per nt ----
        uint32_t phi[4][4];
        const bool full = (n0g + BN <= vl);
        #pragma unroll
        for (int nt = 0; nt < 8; nt++){
            float sc4[4] = {0.f, 0.f, 0.f, 0.f};
            uint32_t kh[8];
            uint32_t base = (uint32_t)(8*nt + (ln & 7)) * SKB
                          + (uint32_t)((ln >> 3) & 1) * 16
                          + (uint32_t)(ln >> 4) * 32;
            ldsm4(kh + 0, sb + SM_KH + base);
            ldsm4(kh + 4, sb + SM_KH + base + 64);
            #pragma unroll
            for (int ks = 0; ks < 4; ks++)
                mma16816(sc4, qh[ks], kh[2*ks], kh[2*ks+1]);

            uint32_t h01, h23;
            if (full){
                h01 = cvt2h(sc4[0], sc4[1]);
                h23 = cvt2h(sc4[2], sc4[3]);
            } else {
                int c0 = n0g + nt*8 + 2*tg;
                h01 = cvt2h((c0     < vl) ? sc4[0] : -1e30f,
                            (c0 + 1 < vl) ? sc4[1] : -1e30f);
                h23 = cvt2h((c0     < vl) ? sc4[2] : -1e30f,
                            (c0 + 1 < vl) ? sc4[3] : -1e30f);
            }
            int j = nt >> 1, hf = (nt & 1) * 2;
            phi[j][hf + 0] = ex2h2(h01);
            phi[j][hf + 1] = ex2h2(h23);
        }

        // ---- row sums via MMA with ones-B ----
        #pragma unroll
        for (int ks = 0; ks < 4; ks++)
            mma16816(lc, phi[ks], HONES, HONES);

        // ---- O += ph * vh ----
        #pragma unroll
        for (int nt = 0; nt < 8; nt++){
            uint32_t vh[8];
            uint32_t base = (uint32_t)ln * SKB + (uint32_t)nt * 16;
            ldsm4t(vh + 0, sb + SM_VH + base);
            ldsm4t(vh + 4, sb + SM_VH + base + 32u * SKB);
            #pragma unroll
            for (int ks = 0; ks < 4; ks++)
                mma16816(oc[nt], phi[ks], vh[2*ks], vh[2*ks+1]);
        }
    }

    const int rg0 = b * Lq + q0 + 16*w + g;

    if (nact == 1){
        // ---- single chunk: normalize in-register, write O directly ----
        const float inv0 = 1.f / lc[0];
        const float inv1 = 1.f / lc[2];
        float* O0 = O + (size_t)rg0 * DH;
        float* O1 = O0 + (size_t)8 * DH;
        #pragma unroll
        for (int nt = 0; nt < 8; nt++){
            float2 a0, a1;
            a0.x = oc[nt][0] * inv0; a0.y = oc[nt][1] * inv0;
            a1.x = oc[nt][2] * inv1; a1.y = oc[nt][3] * inv1;
            *(float2*)(O0 + nt*8 + 2*tg) = a0;
            *(float2*)(O1 + nt*8 + 2*tg) = a1;
        }
        return;
    }

    // ---- write unnormalized partials to scratch ----
    float* Op0 = g_Opart + ((size_t)c * R + rg0) * DH;
    float* Op1 = Op0 + (size_t)8 * DH;
    if (tg == 0){
        g_lpart[(size_t)c * R + rg0]     = lc[0];
        g_lpart[(size_t)c * R + rg0 + 8] = lc[2];
    }
    #pragma unroll
    for (int nt = 0; nt < 8; nt++){
        float2 a0, a1;
        a0.x = oc[nt][0]; a0.y = oc[nt][1];
        a1.x = oc[nt][2]; a1.y = oc[nt][3];
        *(float2*)(Op0 + nt*8 + 2*tg) = a0;
        *(float2*)(Op1 + nt*8 + 2*tg) = a1;
    }
}

// ---------------- Phase 2: combine chunk partials + normalize ----------------
__global__ __launch_bounds__(256, 8)
void fa_combine_kernel(const int* __restrict__ vlen, float* __restrict__ O,
                       int Lq, int Lk, int B, int ck)
{
    const int idx = blockIdx.x * blockDim.x + threadIdx.x;
    const int total = B * Lq * (DH / 4);
    if (idx >= total) return;

    const int rd = idx >> 4;
    const int d4 = idx & 15;
    const int b  = rd / Lq;
    const int R  = B * Lq;

    int vl = vlen[b];
    if (vl < 1) vl = 1;
    if (vl > Lk) vl = Lk;
    const int nact = (vl + ck - 1) / ck;
    if (nact == 1) return;              // O already written by part

    float4 p[NCH_MAX];
    float  lp[NCH_MAX];
    #pragma unroll
    for (int c = 0; c < NCH_MAX; c++){
        if (c < nact){
            p[c]  = *(const float4*)(g_Opart + ((size_t)c * R + rd) * DH + d4 * 4);
            lp[c] = g_lpart[(size_t)c * R + rd];
        } else {
            p[c]  = make_float4(0.f, 0.f, 0.f, 0.f);
            lp[c] = 0.f;
        }
    }
    float4 acc = make_float4(0.f, 0.f, 0.f, 0.f);
    float l = 0.f;
    #pragma unroll
    for (int c = 0; c < NCH_MAX; c++){
        acc.x += p[c].x; acc.y += p[c].y;
        acc.z += p[c].z; acc.w += p[c].w;
        l     += lp[c];
    }
    const float inv = 1.f / l;
    acc.x *= inv; acc.y *= inv; acc.z *= inv; acc.w *= inv;
    *(float4*)(O + (size_t)rd * DH + d4 * 4) = acc;
}

extern "C" void kernel_launch(void* const* d_in, const int* in_sizes, int n_in,
                              void* d_out, int out_size)
{
    const float* Q  = (const float*)d_in[0];
    const float* K  = (const float*)d_in[1];
    const float* V  = (const float*)d_in[2];
    const int*   vl = (const int*)d_in[3];
    float*       O  = (float*)d_out;

    const int B  = in_sizes[3];
    const int Lq = in_sizes[0] / (B * DH);
    const int Lk = in_sizes[1] / (B * DH);

    int ck = ((Lk + NCH_MAX * BN - 1) / (NCH_MAX * BN)) * BN;
    if (ck < BN) ck = BN;
    const int nch = (Lk + ck - 1) / ck;

    const int n8 = (B * Lk * DH) / 8;
    fa_cvt_kernel<<<(n8 + 255) / 256, 256>>>(K, V, vl, Lk, n8);

    cudaFuncSetAttribute(fa_part_kernel,
                         cudaFuncAttributeMaxDynamicSharedMemorySize, SM_TOTAL);

    dim3 grid1(Lq / BM, B, nch);
    fa_part_kernel<<<grid1, 256, SM_TOTAL>>>(Q, vl, O, Lq, Lk, ck);

    const int total = B * Lq * (DH / 4);
    fa_combine_kernel<<<(total + 255) / 256, 256>>>(vl, O, Lq, Lk, B, ck);
}

// round 16
// speedup vs baseline: 1.0261x; 1.0261x over previous
#include <cuda_runtime.h>
#include <cuda_fp16.h>
#include <cstdint>

#define DH 64
#define BM 128
#define BN 64
#define SKB 144          // smem row stride bytes (72 fp16) -> ldmatrix conflict-free

#define SM_QH   0
#define QH_SZ   (BM*SKB)              // 18432
#define BUF_SZ  (2*BN*SKB)            // 18432 (KH 9216 + VH 9216)
#define OF_VH   (BN*SKB)              // 9216 within buffer
#define SM_B0   QH_SZ                 // 18432
#define SM_TOTAL (QH_SZ + 2*BUF_SZ)   // 55296 B -> 2 CTAs/SM

#define MAXROWS 16384
#define NCH_MAX 4

__device__ float g_Opart[(size_t)NCH_MAX * MAXROWS * DH];
__device__ float g_lpart[(size_t)NCH_MAX * MAXROWS];
__device__ uint4 g_Kh[(size_t)MAXROWS * DH / 8];
__device__ uint4 g_Vh[(size_t)MAXROWS * DH / 8];

static __device__ __forceinline__ uint32_t smem_u32(const void* p){
    uint32_t a;
    asm("{ .reg .u64 t; cvta.to.shared.u64 t, %1; cvt.u32.u64 %0, t; }" : "=r"(a) : "l"(p));
    return a;
}
static __device__ __forceinline__ uint32_t cvt2h(float a, float b){
    __half2 h = __floats2half2_rn(a, b);
    return *reinterpret_cast<uint32_t*>(&h);
}
static __device__ __forceinline__ uint32_t ex2h2(uint32_t x){
    uint32_t r;
    asm("ex2.approx.f16x2 %0, %1;" : "=r"(r) : "r"(x));
    return r;
}
static __device__ __forceinline__ void cvtH8(const float* f, uint4& out){
    out = make_uint4(cvt2h(f[0], f[1]), cvt2h(f[2], f[3]),
                     cvt2h(f[4], f[5]), cvt2h(f[6], f[7]));
}
static __device__ __forceinline__ void ldsm4(uint32_t* r, uint32_t a){
    asm volatile("ldmatrix.sync.aligned.m8n8.x4.shared.b16 {%0,%1,%2,%3}, [%4];"
                 : "=r"(r[0]), "=r"(r[1]), "=r"(r[2]), "=r"(r[3]) : "r"(a));
}
static __device__ __forceinline__ void ldsm4t(uint32_t* r, uint32_t a){
    asm volatile("ldmatrix.sync.aligned.m8n8.x4.trans.shared.b16 {%0,%1,%2,%3}, [%4];"
                 : "=r"(r[0]), "=r"(r[1]), "=r"(r[2]), "=r"(r[3]) : "r"(a));
}
static __device__ __forceinline__ void mma16816(float* d, const uint32_t* a, uint32_t b0, uint32_t b1){
    asm volatile("mma.sync.aligned.m16n8k16.row.col.f32.f16.f16.f32 "
                 "{%0,%1,%2,%3}, {%4,%5,%6,%7}, {%8,%9}, {%0,%1,%2,%3};"
                 : "+f"(d[0]), "+f"(d[1]), "+f"(d[2]), "+f"(d[3])
                 : "r"(a[0]), "r"(a[1]), "r"(a[2]), "r"(a[3]), "r"(b0), "r"(b1));
}
static __device__ __forceinline__ void cpa16(uint32_t smem_dst, const void* gptr){
    asm volatile("cp.async.cg.shared.global [%0], [%1], 16;"
                 :: "r"(smem_dst), "l"(gptr) : "memory");
}
#define CPA_COMMIT() asm volatile("cp.async.commit_group;" ::: "memory")
#define CPA_WAIT0()  asm volatile("cp.async.wait_group 0;" ::: "memory")

// ---------------- Phase 0: convert K,V fp32 -> fp16 (rows part will read) ----------------
__global__ __launch_bounds__(256, 8)
void fa_cvt_kernel(const float* __restrict__ K, const float* __restrict__ V,
                   const int* __restrict__ vlen, int Lk, int n8)
{
    __shared__ int s_thr;
    const int j = blockIdx.x * blockDim.x + threadIdx.x;
    // all rows in one 256-thread block belong to one batch (16384 uint4/batch % 256 == 0)
    if (threadIdx.x == 0){
        int b = (j >> 3) / Lk;
        int vl = vlen[b];
        if (vl < 1) vl = 1;
        if (vl > Lk) vl = Lk;
        s_thr = ((vl + BN - 1) / BN) * BN;
    }
    __syncthreads();
    if (j >= n8) return;
    const int rloc = (j >> 3) % Lk;
    if (rloc >= s_thr) return;

    const float4* K4 = (const float4*)K;
    const float4* V4 = (const float4*)V;
    float4 a0 = K4[(size_t)j*2], a1 = K4[(size_t)j*2+1];
    float4 b0 = V4[(size_t)j*2], b1 = V4[(size_t)j*2+1];
    float f[8]; uint4 u;
    *(float4*)(f) = a0; *(float4*)(f+4) = a1; cvtH8(f, u); g_Kh[j] = u;
    *(float4*)(f) = b0; *(float4*)(f+4) = b1; cvtH8(f, u); g_Vh[j] = u;
}

// ---------------- Phase 1: partial attention over one key chunk ----------------
__global__ __launch_bounds__(256, 2)
void fa_part_kernel(const float* __restrict__ Q, const int* __restrict__ vlen,
                    float* __restrict__ O, int Lq, int Lk, int ck)
{
    extern __shared__ char smem[];
    const uint32_t sb = smem_u32(smem);
    const int t  = threadIdx.x;
    const int w  = t >> 5;
    const int ln = t & 31;
    const int g  = ln >> 2;
    const int tg = ln & 3;
    const int b  = blockIdx.y;
    const int q0 = blockIdx.x * BM;
    const int c  = blockIdx.z;

    int vl = vlen[b];
    if (vl < 1) vl = 1;
    if (vl > Lk) vl = Lk;
    const int nact = (vl + ck - 1) / ck;

    const int cstart = c * ck;
    if (cstart >= vl) return;
    const int kend   = (cstart + ck < vl) ? cstart + ck : vl;
    const int ntiles = (kend - cstart + BN - 1) / BN;

    const int B_ = gridDim.y;
    const int R  = B_ * Lq;

    const float* Qb = Q + ((size_t)b * Lq + q0) * DH;
    const uint4* Kb = g_Kh + ((size_t)b * Lk + cstart) * (DH / 8);
    const uint4* Vb = g_Vh + ((size_t)b * Lk + cstart) * (DH / 8);

    // per-thread tile-load assignment: row r4 (0..63), 16B chunks qq*2, qq*2+1
    const int r4 = t >> 2, qq = t & 3;
    const uint32_t st_off = (uint32_t)(r4 * SKB + qq * 32);

    // ---- issue cp.async for tile 0 ----
    {
        const uint4* kp = Kb + (size_t)r4 * (DH/8) + qq * 2;
        const uint4* vp = Vb + (size_t)r4 * (DH/8) + qq * 2;
        uint32_t d = sb + SM_B0 + st_off;
        cpa16(d,            kp);
        cpa16(d + 16,       kp + 1);
        cpa16(d + OF_VH,    vp);
        cpa16(d + OF_VH+16, vp + 1);
        CPA_COMMIT();
    }

    // ---- Q -> smem, pre-scaled by log2e/sqrt(d), single fp16 ----
    {
        int r = t >> 1, h = t & 1;
        const float* qp = Qb + (size_t)r * DH + h * 32;
        float f[32];
        #pragma unroll
        for (int i = 0; i < 8; i++) *(float4*)(f + 4*i) = *(const float4*)(qp + 4*i);
        #pragma unroll
        for (int i = 0; i < 32; i++) f[i] *= 0.18033688f;   // 1.4426950f / 8
        #pragma unroll
        for (int cc = 0; cc < 4; cc++){
            uint4 u; cvtH8(f + 8*cc, u);
            *(uint4*)(smem + SM_QH + r * SKB + (h*4 + cc) * 16) = u;
        }
    }
    __syncthreads();

    // ---- Q A-fragments ----
    uint32_t qh[4][4];
    {
        uint32_t rowoff = (uint32_t)(16*w + (ln & 15)) * SKB + (uint32_t)(ln >> 4) * 16;
        #pragma unroll
        for (int ks = 0; ks < 4; ks++)
            ldsm4(qh[ks], sb + SM_QH + rowoff + ks * 32);
    }

    float oc[8][4];
    #pragma unroll
    for (int nt = 0; nt < 8; nt++)
        #pragma unroll
        for (int j = 0; j < 4; j++) oc[nt][j] = 0.f;
    float lc[4] = {0.f, 0.f, 0.f, 0.f};
    const uint32_t HONES = 0x3C003C00u;   // half2(1,1)

    for (int kt = 0; kt < ntiles; kt++){
        const int n0g = cstart + kt * BN;
        const uint32_t cur = SM_B0 + (uint32_t)(kt & 1) * BUF_SZ;

        CPA_WAIT0();        // tile kt landed (per-thread)
        __syncthreads();    // visible to all; reads of tile kt-1 complete

        // ---- issue cp.async for tile kt+1 into the other buffer ----
        if (kt + 1 < ntiles){
            const uint4* kp = Kb + (size_t)((kt+1)*BN + r4) * (DH/8) + qq * 2;
            const uint4* vp = Vb + (size_t)((kt+1)*BN + r4) * (DH/8) + qq * 2;
            uint32_t d = sb + SM_B0 + (uint32_t)((kt+1) & 1) * BUF_SZ + st_off;
            cpa16(d,            kp);
            cpa16(d + 16,       kp + 1);
            cpa16(d + OF_VH,    vp);
            cpa16(d + OF_VH+16, vp + 1);
            CPA_COMMIT();
        }

        // ---- fused S-MMA + fp16 exp epilogue per nt ----
        uint32_t phi[4][4];
        const bool full = (n0g + BN <= vl);
        #pragma unroll
        for (int nt = 0; nt < 8; nt++){
            float sc4[4] = {0.f, 0.f, 0.f, 0.f};
            uint32_t kh[8];
            uint32_t base = (uint32_t)(8*nt + (ln & 7)) * SKB
                          + (uint32_t)((ln >> 3) & 1) * 16
                          + (uint32_t)(ln >> 4) * 32;
            ldsm4(kh + 0, sb + cur + base);
            ldsm4(kh + 4, sb + cur + base + 64);
            #pragma unroll
            for (int ks = 0; ks < 4; ks++)
                mma16816(sc4, qh[ks], kh[2*ks], kh[2*ks+1]);

            uint32_t h01, h23;
            if (full){
                h01 = cvt2h(sc4[0], sc4[1]);
                h23 = cvt2h(sc4[2], sc4[3]);
            } else {
                int c0 = n0g + nt*8 + 2*tg;
                h01 = cvt2h((c0     < vl) ? sc4[0] : -1e30f,
                            (c0 + 1 < vl) ? sc4[1] : -1e30f);
                h23 = cvt2h((c0     < vl) ? sc4[2] : -1e30f,
                            (c0 + 1 < vl) ? sc4[3] : -1e30f);
            }
            int j = nt >> 1, hf = (nt & 1) * 2;
            phi[j][hf + 0] = ex2h2(h01);
            phi[j][hf + 1] = ex2h2(h23);
        }

        // ---- row sums via MMA with ones-B ----
        #pragma unroll
        for (int ks = 0; ks < 4; ks++)
            mma16816(lc, phi[ks], HONES, HONES);

        // ---- O += ph * vh ----
        #pragma unroll
        for (int nt = 0; nt < 8; nt++){
            uint32_t vh[8];
            uint32_t base = (uint32_t)ln * SKB + (uint32_t)nt * 16;
            ldsm4t(vh + 0, sb + cur + OF_VH + base);
            ldsm4t(vh + 4, sb + cur + OF_VH + base + 32u * SKB);
            #pragma unroll
            for (int ks = 0; ks < 4; ks++)
                mma16816(oc[nt], phi[ks], vh[2*ks], vh[2*ks+1]);
        }
    }

    const int rg0 = b * Lq + q0 + 16*w + g;

    if (nact == 1){
        const float inv0 = 1.f / lc[0];
        const float inv1 = 1.f / lc[2];
        float* O0 = O + (size_t)rg0 * DH;
        float* O1 = O0 + (size_t)8 * DH;
        #pragma unroll
        for (int nt = 0; nt < 8; nt++){
            float2 a0, a1;
            a0.x = oc[nt][0] * inv0; a0.y = oc[nt][1] * inv0;
            a1.x = oc[nt][2] * inv1; a1.y = oc[nt][3] * inv1;
            *(float2*)(O0 + nt*8 + 2*tg) = a0;
            *(float2*)(O1 + nt*8 + 2*tg) = a1;
        }
        return;
    }

    float* Op0 = g_Opart + ((size_t)c * R + rg0) * DH;
    float* Op1 = Op0 + (size_t)8 * DH;
    if (tg == 0){
        g_lpart[(size_t)c * R + rg0]     = lc[0];
        g_lpart[(size_t)c * R + rg0 + 8] = lc[2];
    }
    #pragma unroll
    for (int nt = 0; nt < 8; nt++){
        float2 a0, a1;
        a0.x = oc[nt][0]; a0.y = oc[nt][1];
        a1.x = oc[nt][2]; a1.y = oc[nt][3];
        *(float2*)(Op0 + nt*8 + 2*tg) = a0;
        *(float2*)(Op1 + nt*8 + 2*tg) = a1;
    }
}

// ---------------- Phase 2: combine chunk partials + normalize ----------------
__global__ __launch_bounds__(256, 8)
void fa_combine_kernel(const int* __restrict__ vlen, float* __restrict__ O,
                       int Lq, int Lk, int B, int ck)
{
    const int idx = blockIdx.x * blockDim.x + threadIdx.x;
    const int total = B * Lq * (DH / 4);
    if (idx >= total) return;

    const int rd = idx >> 4;
    const int d4 = idx & 15;
    const int b  = rd / Lq;
    const int R  = B * Lq;

    int vl = vlen[b];
    if (vl < 1) vl = 1;
    if (vl > Lk) vl = Lk;
    const int nact = (vl + ck - 1) / ck;
    if (nact == 1) return;              // O already written by part

    float4 p[NCH_MAX];
    float  lp[NCH_MAX];
    #pragma unroll
    for (int c = 0; c < NCH_MAX; c++){
        if (c < nact){
            p[c]  = *(const float4*)(g_Opart + ((size_t)c * R + rd) * DH + d4 * 4);
            lp[c] = g_lpart[(size_t)c * R + rd];
        } else {
            p[c]  = make_float4(0.f, 0.f, 0.f, 0.f);
            lp[c] = 0.f;
        }
    }
    float4 acc = make_float4(0.f, 0.f, 0.f, 0.f);
    float l = 0.f;
    #pragma unroll
    for (int c = 0; c < NCH_MAX; c++){
        acc.x += p[c].x; acc.y += p[c].y;
        acc.z += p[c].z; acc.w += p[c].w;
        l     += lp[c];
    }
    const float inv = 1.f / l;
    acc.x *= inv; acc.y *= inv; acc.z *= inv; acc.w *= inv;
    *(float4*)(O + (size_t)rd * DH + d4 * 4) = acc;
}

extern "C" void kernel_launch(void* const* d_in, const int* in_sizes, int n_in,
                              void* d_out, int out_size)
{
    const float* Q  = (const float*)d_in[0];
    const float* K  = (const float*)d_in[1];
    const float* V  = (const float*)d_in[2];
    const int*   vl = (const int*)d_in[3];
    float*       O  = (float*)d_out;

    const int B  = in_sizes[3];
    const int Lq = in_sizes[0] / (B * DH);
    const int Lk = in_sizes[1] / (B * DH);

    int ck = ((Lk + NCH_MAX * BN - 1) / (NCH_MAX * BN)) * BN;
    if (ck < BN) ck = BN;
    const int nch = (Lk + ck - 1) / ck;

    const int n8 = (B * Lk * DH) / 8;
    fa_cvt_kernel<<<(n8 + 255) / 256, 256>>>(K, V, vl, Lk, n8);

    cudaFuncSetAttribute(fa_part_kernel,
                         cudaFuncAttributeMaxDynamicSharedMemorySize, SM_TOTAL);

    dim3 grid1(Lq / BM, B, nch);
    fa_part_kernel<<<grid1, 256, SM_TOTAL>>>(Q, vl, O, Lq, Lk, ck);

    const int total = B * Lq * (DH / 4);
    fa_combine_kernel<<<(total + 255) / 256, 256>>>(vl, O, Lq, Lk, B, ck);
}